// round 2
// baseline (speedup 1.0000x reference)
#include <cuda_runtime.h>

#define NROWS 65536
#define FDIM  64
#define EDIM  16
#define NH1   8
#define NH2   4
#define BN_EPS 1e-5f
#define NPART 512

// ---- device scratch (no allocs allowed) ----
__device__ float g_part[NPART * FDIM];    // Xc column partial sums
__device__ float g_hstat[2 * NH1];        // [0..7]=sum h_j, [8..15]=sum h_j^2
__device__ float g_k[FDIM];               // w2*xc_mean + b2
__device__ float g_U[FDIM * EDIM];        // W1+W2
__device__ float g_S[FDIM * 48];          // per f: U(4 f4), B1(4 f4), B2(4 f4)
__device__ float g_Mh[FDIM * 24];         // per f: P[8],Q[8],R[8]
__device__ float g_quad[FDIM * 8];        // per f: m0..m5 (m3..m5 pre-doubled), pad
__device__ float g_h[NROWS * NH1];        // 2MB h scratch

// ---------------- K1: Xc column partial sums (no atomics, no pre-zero) ----------------
__global__ void __launch_bounds__(256) k_xcsum(const float* __restrict__ Xc) {
    __shared__ float4 sp[256];
    int f4 = threadIdx.x & 15;
    int rg = threadIdx.x >> 4;
    float4 acc = make_float4(0.f, 0.f, 0.f, 0.f);
    int r = blockIdx.x * 16 + rg;
    #pragma unroll
    for (int it = 0; it < NROWS / (NPART * 16); it++, r += NPART * 16) {
        float4 v = ((const float4*)Xc)[(size_t)r * 16 + f4];
        acc.x += v.x; acc.y += v.y; acc.z += v.z; acc.w += v.w;
    }
    sp[threadIdx.x] = acc;
    __syncthreads();
    if (threadIdx.x < 16) {
        float4 t = make_float4(0.f, 0.f, 0.f, 0.f);
        #pragma unroll
        for (int g = 0; g < 16; g++) {
            float4 v = sp[g * 16 + threadIdx.x];
            t.x += v.x; t.y += v.y; t.z += v.z; t.w += v.w;
        }
        ((float4*)g_part)[blockIdx.x * 16 + threadIdx.x] = t;
    }
}

// ---------------- K2: reduce partials + derived constants (1 block) ----------------
__global__ void __launch_bounds__(256) k_setup(
    const float* __restrict__ w2, const float* __restrict__ b2,
    const float* __restrict__ W1, const float* __restrict__ W2p,
    const float* __restrict__ B1, const float* __restrict__ B2,
    const float* __restrict__ L1w)
{
    __shared__ float4 red[256];
    __shared__ float  sXc[FDIM];
    int tid = threadIdx.x;

    {
        int col4 = tid & 15, grp = tid >> 4;
        float4 acc = make_float4(0.f, 0.f, 0.f, 0.f);
        for (int p = grp; p < NPART; p += 16) {
            float4 v = ((const float4*)g_part)[p * 16 + col4];
            acc.x += v.x; acc.y += v.y; acc.z += v.z; acc.w += v.w;
        }
        red[tid] = acc;
    }
    if (tid < 2 * NH1) g_hstat[tid] = 0.f;
    __syncthreads();
    if (tid < 16) {
        float4 t = make_float4(0.f, 0.f, 0.f, 0.f);
        #pragma unroll
        for (int g = 0; g < 16; g++) {
            float4 v = red[g * 16 + tid];
            t.x += v.x; t.y += v.y; t.z += v.z; t.w += v.w;
        }
        sXc[tid * 4 + 0] = t.x; sXc[tid * 4 + 1] = t.y;
        sXc[tid * 4 + 2] = t.z; sXc[tid * 4 + 3] = t.w;
    }

    for (int idx = tid; idx < FDIM * EDIM; idx += 256) {
        float u = W1[idx] + W2p[idx];
        g_U[idx] = u;
    }
    __syncthreads();

    // pack g_S: per f 12 float4s = U, B1, B2
    {
        const float4* U4  = (const float4*)g_U;
        const float4* B14 = (const float4*)B1;
        const float4* B24 = (const float4*)B2;
        float4* S4 = (float4*)g_S;
        for (int idx = tid; idx < FDIM * 4; idx += 256) {
            int f = idx >> 2, j = idx & 3;
            S4[f * 12 + j]     = U4[idx];
            S4[f * 12 + 4 + j] = B14[idx];
            S4[f * 12 + 8 + j] = B24[idx];
        }
    }

    if (tid < FDIM) {
        float xcm = sXc[tid] * (1.0f / NROWS);
        g_k[tid] = w2[tid] * xcm + b2[tid];
        float m0 = 0, m1 = 0, m2 = 0, m3 = 0, m4 = 0, m5 = 0;
        for (int e = 0; e < EDIM; e++) {
            float u = g_U[tid * EDIM + e];
            float x = B1[tid * EDIM + e];
            float y = B2[tid * EDIM + e];
            m0 += u * u; m1 += x * x; m2 += y * y;
            m3 += u * x; m4 += u * y; m5 += x * y;
        }
        g_quad[tid * 8 + 0] = m0;
        g_quad[tid * 8 + 1] = m1;
        g_quad[tid * 8 + 2] = m2;
        g_quad[tid * 8 + 3] = 2.f * m3;
        g_quad[tid * 8 + 4] = 2.f * m4;
        g_quad[tid * 8 + 5] = 2.f * m5;
        g_quad[tid * 8 + 6] = 0.f;
        g_quad[tid * 8 + 7] = 0.f;
    }
    for (int idx = tid; idx < FDIM * NH1; idx += 256) {
        int f = idx >> 3, j = idx & 7;
        const float* lr = L1w + j * (FDIM * EDIM) + f * EDIM;
        float P = 0, Q = 0, R = 0;
        for (int e = 0; e < EDIM; e++) {
            float l = lr[e];
            P += g_U[f * EDIM + e] * l;
            Q += B1[f * EDIM + e] * l;
            R += B2[f * EDIM + e] * l;
        }
        g_Mh[f * 24 + j]      = P;
        g_Mh[f * 24 + 8 + j]  = Q;
        g_Mh[f * 24 + 16 + j] = R;
    }
}

// ---------------- K3: main per-row pass, 2 lanes per row (split-f) ----------------
__global__ void __launch_bounds__(256) k_main(
    const float* __restrict__ Xa, const float* __restrict__ Xc,
    const float* __restrict__ w1, const float* __restrict__ b1,
    const float* __restrict__ lin1_b, float* __restrict__ out)
{
    __shared__ float4 sS[FDIM * 12];
    __shared__ float4 sMh[FDIM * 6];
    __shared__ float4 sQ[FDIM * 2];
    __shared__ float4 sFF[FDIM];
    __shared__ float  sStat[2 * NH1];

    int tid = threadIdx.x;
    {
        const float4* S4 = (const float4*)g_S;
        for (int idx = tid; idx < FDIM * 12; idx += 256) sS[idx] = S4[idx];
        const float4* M4 = (const float4*)g_Mh;
        for (int idx = tid; idx < FDIM * 6; idx += 256) sMh[idx] = M4[idx];
        const float4* q4 = (const float4*)g_quad;
        for (int idx = tid; idx < FDIM * 2; idx += 256) sQ[idx] = q4[idx];
        if (tid < FDIM) sFF[tid] = make_float4(w1[tid], b1[tid], g_k[tid], 0.f);
        if (tid < 2 * NH1) sStat[tid] = 0.f;
    }
    __syncthreads();

    int half = tid & 1;
    int i = blockIdx.x * 128 + (tid >> 1);
    const float4* A4 = (const float4*)Xa + (size_t)i * 16 + half * 8;
    const float4* C4 = (const float4*)Xc + (size_t)i * 16 + half * 8;

    float sE[EDIM];
    float hv[NH1];
    #pragma unroll
    for (int e = 0; e < EDIM; e++) sE[e] = 0.f;
    #pragma unroll
    for (int j = 0; j < NH1; j++) hv[j] = 0.f;
    float q = 0.f, ff = 0.f;

    #pragma unroll 2
    for (int ch = 0; ch < 8; ch++) {
        float4 a4 = A4[ch];
        float4 c4 = C4[ch];
        float av[4] = {a4.x, a4.y, a4.z, a4.w};
        float cv[4] = {c4.x, c4.y, c4.z, c4.w};
        #pragma unroll
        for (int u = 0; u < 4; u++) {
            int f = half * 32 + ch * 4 + u;
            float a = av[u], c = cv[u];
            float ac = a * c;
            float4 w = sFF[f];
            ff += ac * w.x;
            ff += c * w.y;
            ff += a * w.z;
            float4 q0 = sQ[f * 2], q1 = sQ[f * 2 + 1];
            q += (ac * ac) * q0.x;
            q += (c * c)   * q0.y;
            q += (a * a)   * q0.z;
            q += (ac * c)  * q0.w;
            q += (ac * a)  * q1.x;
            q += ac        * q1.y;
            const float4* sp = &sS[f * 12];
            #pragma unroll
            for (int e4 = 0; e4 < 4; e4++) {
                float4 uu  = sp[e4];
                float4 bb1 = sp[4 + e4];
                float4 bb2 = sp[8 + e4];
                sE[e4 * 4 + 0] += ac * uu.x + c * bb1.x + a * bb2.x;
                sE[e4 * 4 + 1] += ac * uu.y + c * bb1.y + a * bb2.y;
                sE[e4 * 4 + 2] += ac * uu.z + c * bb1.z + a * bb2.z;
                sE[e4 * 4 + 3] += ac * uu.w + c * bb1.w + a * bb2.w;
            }
            const float4* mh = &sMh[f * 6];
            #pragma unroll
            for (int j4 = 0; j4 < 2; j4++) {
                float4 P = mh[j4], Q4 = mh[2 + j4], R = mh[4 + j4];
                hv[j4 * 4 + 0] += ac * P.x + c * Q4.x + a * R.x;
                hv[j4 * 4 + 1] += ac * P.y + c * Q4.y + a * R.y;
                hv[j4 * 4 + 2] += ac * P.z + c * Q4.z + a * R.z;
                hv[j4 * 4 + 3] += ac * P.w + c * Q4.w + a * R.w;
            }
        }
    }

    #pragma unroll
    for (int e = 0; e < EDIM; e++) sE[e] += __shfl_xor_sync(0xffffffffu, sE[e], 1);
    #pragma unroll
    for (int j = 0; j < NH1; j++) hv[j] += __shfl_xor_sync(0xffffffffu, hv[j], 1);
    q  += __shfl_xor_sync(0xffffffffu, q, 1);
    ff += __shfl_xor_sync(0xffffffffu, ff, 1);

    float ss = 0.f;
    #pragma unroll
    for (int e = 0; e < EDIM; e++) ss += sE[e] * sE[e];
    float fm2 = 0.5f * (ss - q) * (1.0f / EDIM);

    #pragma unroll
    for (int j = 0; j < NH1; j++) hv[j] += __ldg(&lin1_b[j]);

    if (half == 0) {
        out[i] = ff * (1.0f / FDIM) + fm2;
        float4* hout = (float4*)g_h + (size_t)i * 2;
        hout[0] = make_float4(hv[0], hv[1], hv[2], hv[3]);
        hout[1] = make_float4(hv[4], hv[5], hv[6], hv[7]);
    }

    float mask = (half == 0) ? 1.f : 0.f;
    float st[16];
    #pragma unroll
    for (int j = 0; j < NH1; j++) { st[j] = mask * hv[j]; st[8 + j] = mask * hv[j] * hv[j]; }
    #pragma unroll
    for (int off = 16; off; off >>= 1) {
        #pragma unroll
        for (int j = 0; j < 16; j++)
            st[j] += __shfl_xor_sync(0xffffffffu, st[j], off);
    }
    if ((tid & 31) == 0) {
        #pragma unroll
        for (int j = 0; j < 16; j++) atomicAdd(&sStat[j], st[j]);
    }
    __syncthreads();
    if (tid < 16) atomicAdd(&g_hstat[tid], sStat[tid]);
}

// ---------------- K4: BN finalize (per block) + tanh + lin2 epilogue ----------------
__global__ void __launch_bounds__(256) k_deep(
    const float* __restrict__ gamma, const float* __restrict__ beta,
    const float* __restrict__ l2w, const float* __restrict__ l2b,
    float* __restrict__ out)
{
    __shared__ float fin[32];
    int tid = threadIdx.x;
    if (tid < NH1) {
        float mu  = g_hstat[tid] * (1.0f / NROWS);
        float var = g_hstat[NH1 + tid] * (1.0f / NROWS) - mu * mu;
        float rs  = rsqrtf(var + BN_EPS);
        float al  = gamma[tid] * rs;
        fin[tid] = al;
        fin[8 + tid] = beta[tid] - mu * al;
        float v = 0.f;
        #pragma unroll
        for (int j = 0; j < NH2; j++) v += l2w[j * NH1 + tid];
        fin[16 + tid] = v * (1.0f / NH2);
    }
    if (tid == 0) {
        float cb = 0.f;
        #pragma unroll
        for (int j = 0; j < NH2; j++) cb += l2b[j];
        fin[24] = cb * (1.0f / NH2);
    }
    __syncthreads();
    int i = blockIdx.x * 256 + tid;
    const float4* h4 = (const float4*)g_h + (size_t)i * 2;
    float4 hA = h4[0], hB = h4[1];
    float hvv[8] = {hA.x, hA.y, hA.z, hA.w, hB.x, hB.y, hB.z, hB.w};
    float acc = fin[24];
    #pragma unroll
    for (int j = 0; j < NH1; j++)
        acc += fin[16 + j] * tanhf(fin[j] * hvv[j] + fin[8 + j]);
    out[i] += acc;
}

extern "C" void kernel_launch(void* const* d_in, const int* in_sizes, int n_in,
                              void* d_out, int out_size)
{
    const float* Xa     = (const float*)d_in[0];
    const float* Xc     = (const float*)d_in[1];
    const float* w1     = (const float*)d_in[2];
    const float* b1     = (const float*)d_in[3];
    const float* w2     = (const float*)d_in[4];
    const float* b2     = (const float*)d_in[5];
    const float* W1     = (const float*)d_in[6];
    const float* B1     = (const float*)d_in[7];
    const float* W2     = (const float*)d_in[8];
    const float* B2     = (const float*)d_in[9];
    const float* L1w    = (const float*)d_in[10];
    const float* L1b    = (const float*)d_in[11];
    const float* g1     = (const float*)d_in[12];
    const float* be1    = (const float*)d_in[13];
    const float* L2w    = (const float*)d_in[14];
    const float* L2b    = (const float*)d_in[15];
    float* out = (float*)d_out;

    k_xcsum<<<NPART, 256>>>(Xc);
    k_setup<<<1, 256>>>(w2, b2, W1, W2, B1, B2, L1w);
    k_main<<<NROWS / 128, 256>>>(Xa, Xc, w1, b1, L1b, out);
    k_deep<<<NROWS / 256, 256>>>(g1, be1, L2w, L2b, out);
}

// round 3
// speedup vs baseline: 1.7529x; 1.7529x over previous
#include <cuda_runtime.h>

#define NROWS 65536
#define FDIM  64
#define EDIM  16
#define NH1   8
#define NH2   4
#define BN_EPS 1e-5f
#define NPART 512
#define HROWS (NROWS / 2)

typedef unsigned long long u64;

// ---- device scratch ----
__device__ float g_part[NPART * FDIM];
__device__ float g_hstat[2 * NH1];
__device__ float g_k[FDIM];
__device__ float g_U[FDIM * EDIM];
__device__ float g_S[FDIM * 48];     // per f: U[16], B1[16], B2[16]
__device__ float g_Mh[FDIM * 24];    // per f: P[8],Q[8],R[8]
__device__ float g_quad[FDIM * 8];   // per f: m0,m1,m2,2m3,2m4,2m5,0,0
__device__ float g_h[NROWS * NH1];

// ---- f32x2 helpers ----
__device__ __forceinline__ u64 pk2(float x, float y) {
    u64 r; asm("mov.b64 %0, {%1,%2};" : "=l"(r) : "f"(x), "f"(y)); return r;
}
__device__ __forceinline__ u64 fma2(u64 a, u64 b, u64 c) {
    u64 d; asm("fma.rn.f32x2 %0, %1, %2, %3;" : "=l"(d) : "l"(a), "l"(b), "l"(c)); return d;
}
__device__ __forceinline__ float2 upk(u64 v) {
    float2 r; asm("mov.b64 {%0,%1}, %2;" : "=f"(r.x), "=f"(r.y) : "l"(v)); return r;
}

// ---------------- K1: Xc column partial sums ----------------
__global__ void __launch_bounds__(256) k_xcsum(const float* __restrict__ Xc) {
    __shared__ float4 sp[256];
    int f4 = threadIdx.x & 15;
    int rg = threadIdx.x >> 4;
    float4 acc = make_float4(0.f, 0.f, 0.f, 0.f);
    int r = blockIdx.x * 16 + rg;
    #pragma unroll
    for (int it = 0; it < NROWS / (NPART * 16); it++, r += NPART * 16) {
        float4 v = ((const float4*)Xc)[(size_t)r * 16 + f4];
        acc.x += v.x; acc.y += v.y; acc.z += v.z; acc.w += v.w;
    }
    sp[threadIdx.x] = acc;
    __syncthreads();
    if (threadIdx.x < 16) {
        float4 t = make_float4(0.f, 0.f, 0.f, 0.f);
        #pragma unroll
        for (int g = 0; g < 16; g++) {
            float4 v = sp[g * 16 + threadIdx.x];
            t.x += v.x; t.y += v.y; t.z += v.z; t.w += v.w;
        }
        ((float4*)g_part)[blockIdx.x * 16 + threadIdx.x] = t;
    }
}

// ---------------- K2: reduce partials + derived constants ----------------
__global__ void __launch_bounds__(256) k_setup(
    const float* __restrict__ w2, const float* __restrict__ b2,
    const float* __restrict__ W1, const float* __restrict__ W2p,
    const float* __restrict__ B1, const float* __restrict__ B2,
    const float* __restrict__ L1w)
{
    __shared__ float4 red[256];
    __shared__ float  sXc[FDIM];
    int tid = threadIdx.x;
    {
        int col4 = tid & 15, grp = tid >> 4;
        float4 acc = make_float4(0.f, 0.f, 0.f, 0.f);
        for (int p = grp; p < NPART; p += 16) {
            float4 v = ((const float4*)g_part)[p * 16 + col4];
            acc.x += v.x; acc.y += v.y; acc.z += v.z; acc.w += v.w;
        }
        red[tid] = acc;
    }
    if (tid < 2 * NH1) g_hstat[tid] = 0.f;
    __syncthreads();
    if (tid < 16) {
        float4 t = make_float4(0.f, 0.f, 0.f, 0.f);
        #pragma unroll
        for (int g = 0; g < 16; g++) {
            float4 v = red[g * 16 + tid];
            t.x += v.x; t.y += v.y; t.z += v.z; t.w += v.w;
        }
        sXc[tid * 4 + 0] = t.x; sXc[tid * 4 + 1] = t.y;
        sXc[tid * 4 + 2] = t.z; sXc[tid * 4 + 3] = t.w;
    }
    for (int idx = tid; idx < FDIM * EDIM; idx += 256)
        g_U[idx] = W1[idx] + W2p[idx];
    __syncthreads();
    {
        const float4* U4  = (const float4*)g_U;
        const float4* B14 = (const float4*)B1;
        const float4* B24 = (const float4*)B2;
        float4* S4 = (float4*)g_S;
        for (int idx = tid; idx < FDIM * 4; idx += 256) {
            int f = idx >> 2, j = idx & 3;
            S4[f * 12 + j]     = U4[idx];
            S4[f * 12 + 4 + j] = B14[idx];
            S4[f * 12 + 8 + j] = B24[idx];
        }
    }
    if (tid < FDIM) {
        float xcm = sXc[tid] * (1.0f / NROWS);
        g_k[tid] = w2[tid] * xcm + b2[tid];
        float m0 = 0, m1 = 0, m2 = 0, m3 = 0, m4 = 0, m5 = 0;
        for (int e = 0; e < EDIM; e++) {
            float u = g_U[tid * EDIM + e];
            float x = B1[tid * EDIM + e];
            float y = B2[tid * EDIM + e];
            m0 += u * u; m1 += x * x; m2 += y * y;
            m3 += u * x; m4 += u * y; m5 += x * y;
        }
        g_quad[tid * 8 + 0] = m0;
        g_quad[tid * 8 + 1] = m1;
        g_quad[tid * 8 + 2] = m2;
        g_quad[tid * 8 + 3] = 2.f * m3;
        g_quad[tid * 8 + 4] = 2.f * m4;
        g_quad[tid * 8 + 5] = 2.f * m5;
        g_quad[tid * 8 + 6] = 0.f;
        g_quad[tid * 8 + 7] = 0.f;
    }
    for (int idx = tid; idx < FDIM * NH1; idx += 256) {
        int f = idx >> 3, j = idx & 7;
        const float* lr = L1w + j * (FDIM * EDIM) + f * EDIM;
        float P = 0, Q = 0, R = 0;
        for (int e = 0; e < EDIM; e++) {
            float l = lr[e];
            P += g_U[f * EDIM + e] * l;
            Q += B1[f * EDIM + e] * l;
            R += B2[f * EDIM + e] * l;
        }
        g_Mh[f * 24 + j]      = P;
        g_Mh[f * 24 + 8 + j]  = Q;
        g_Mh[f * 24 + 16 + j] = R;
    }
}

// ---------------- K3: main pass — 1 thread handles rows i and i+HROWS ----------------
__global__ void __launch_bounds__(256) k_main(
    const float* __restrict__ Xa, const float* __restrict__ Xc,
    const float* __restrict__ w1, const float* __restrict__ b1,
    const float* __restrict__ lin1_b, float* __restrict__ out)
{
    __shared__ ulonglong2 sS[FDIM * 12];   // per f: U ull2[0..3], B1 [4..7], B2 [8..11]
    __shared__ ulonglong2 sMh[FDIM * 6];   // per f: P ull2[0..1], Q [2..3], R [4..5]
    __shared__ float4     sQ[FDIM * 2];
    __shared__ ulonglong2 sFF[FDIM];       // per f: {(w1,b1),(k,0)}
    __shared__ float      sStat[2 * NH1];

    int tid = threadIdx.x;
    {
        const ulonglong2* S2 = (const ulonglong2*)g_S;
        for (int idx = tid; idx < FDIM * 12; idx += 256) sS[idx] = S2[idx];
        const ulonglong2* M2 = (const ulonglong2*)g_Mh;
        for (int idx = tid; idx < FDIM * 6; idx += 256) sMh[idx] = M2[idx];
        const float4* q4 = (const float4*)g_quad;
        for (int idx = tid; idx < FDIM * 2; idx += 256) sQ[idx] = q4[idx];
        if (tid < FDIM) {
            ulonglong2 v;
            v.x = pk2(w1[tid], b1[tid]);
            v.y = pk2(g_k[tid], 0.f);
            sFF[tid] = v;
        }
        if (tid < 2 * NH1) sStat[tid] = 0.f;
    }
    __syncthreads();

    int i1 = blockIdx.x * 256 + tid;
    int i2 = i1 + HROWS;
    const float4* A1 = (const float4*)Xa + (size_t)i1 * 16;
    const float4* C1 = (const float4*)Xc + (size_t)i1 * 16;
    const float4* A2 = (const float4*)Xa + (size_t)i2 * 16;
    const float4* C2 = (const float4*)Xc + (size_t)i2 * 16;

    u64 sE_1[8], sE_2[8], hv_1[4], hv_2[4];
    u64 ff_1 = 0ull, ff_2 = 0ull;
    float q_1 = 0.f, q_2 = 0.f;
    #pragma unroll
    for (int e = 0; e < 8; e++) { sE_1[e] = 0ull; sE_2[e] = 0ull; }
    #pragma unroll
    for (int j = 0; j < 4; j++) { hv_1[j] = 0ull; hv_2[j] = 0ull; }

    #pragma unroll 2
    for (int ch = 0; ch < 16; ch++) {
        float4 a41 = A1[ch], c41 = C1[ch];
        float4 a42 = A2[ch], c42 = C2[ch];
        float av1[4] = {a41.x, a41.y, a41.z, a41.w};
        float cv1[4] = {c41.x, c41.y, c41.z, c41.w};
        float av2[4] = {a42.x, a42.y, a42.z, a42.w};
        float cv2[4] = {c42.x, c42.y, c42.z, c42.w};
        #pragma unroll
        for (int u = 0; u < 4; u++) {
            int f = ch * 4 + u;
            float a1 = av1[u], c1 = cv1[u], ac1 = a1 * c1;
            float a2 = av2[u], c2 = cv2[u], ac2 = a2 * c2;
            u64 aa1 = pk2(a1, a1), cc1 = pk2(c1, c1), acac1 = pk2(ac1, ac1);
            u64 aa2 = pk2(a2, a2), cc2 = pk2(c2, c2), acac2 = pk2(ac2, ac2);

            // fm_first (packed): lane0 accumulates ac*w1 + a*k, lane1 c*b1
            ulonglong2 ffv = sFF[f];
            ff_1 = fma2(pk2(ac1, c1), ffv.x, ff_1);
            ff_1 = fma2(aa1, ffv.y, ff_1);
            ff_2 = fma2(pk2(ac2, c2), ffv.x, ff_2);
            ff_2 = fma2(aa2, ffv.y, ff_2);

            // quad (scalar)
            float4 q0 = sQ[f * 2], q1v = sQ[f * 2 + 1];
            q_1 += (ac1 * ac1) * q0.x + (c1 * c1) * q0.y + (a1 * a1) * q0.z
                 + (ac1 * c1) * q0.w + (ac1 * a1) * q1v.x + ac1 * q1v.y;
            q_2 += (ac2 * ac2) * q0.x + (c2 * c2) * q0.y + (a2 * a2) * q0.z
                 + (ac2 * c2) * q0.w + (ac2 * a2) * q1v.x + ac2 * q1v.y;

            // s[e] matvec, packed pairs, constants shared by both rows
            const ulonglong2* sp = &sS[f * 12];
            #pragma unroll
            for (int g = 0; g < 4; g++) {
                ulonglong2 uu = sp[g];
                ulonglong2 bb1 = sp[4 + g];
                ulonglong2 bb2 = sp[8 + g];
                sE_1[2*g]   = fma2(uu.x, acac1, sE_1[2*g]);
                sE_1[2*g+1] = fma2(uu.y, acac1, sE_1[2*g+1]);
                sE_2[2*g]   = fma2(uu.x, acac2, sE_2[2*g]);
                sE_2[2*g+1] = fma2(uu.y, acac2, sE_2[2*g+1]);
                sE_1[2*g]   = fma2(bb1.x, cc1, sE_1[2*g]);
                sE_1[2*g+1] = fma2(bb1.y, cc1, sE_1[2*g+1]);
                sE_2[2*g]   = fma2(bb1.x, cc2, sE_2[2*g]);
                sE_2[2*g+1] = fma2(bb1.y, cc2, sE_2[2*g+1]);
                sE_1[2*g]   = fma2(bb2.x, aa1, sE_1[2*g]);
                sE_1[2*g+1] = fma2(bb2.y, aa1, sE_1[2*g+1]);
                sE_2[2*g]   = fma2(bb2.x, aa2, sE_2[2*g]);
                sE_2[2*g+1] = fma2(bb2.y, aa2, sE_2[2*g+1]);
            }
            // h matvec, packed
            const ulonglong2* mh = &sMh[f * 6];
            ulonglong2 P = mh[0], Q2 = mh[1];
            ulonglong2 Pq = mh[2], Qq = mh[3];
            ulonglong2 Pr = mh[4], Qr = mh[5];
            hv_1[0] = fma2(P.x,  acac1, hv_1[0]);
            hv_1[1] = fma2(P.y,  acac1, hv_1[1]);
            hv_1[2] = fma2(Q2.x, acac1, hv_1[2]);
            hv_1[3] = fma2(Q2.y, acac1, hv_1[3]);
            hv_1[0] = fma2(Pq.x, cc1, hv_1[0]);
            hv_1[1] = fma2(Pq.y, cc1, hv_1[1]);
            hv_1[2] = fma2(Qq.x, cc1, hv_1[2]);
            hv_1[3] = fma2(Qq.y, cc1, hv_1[3]);
            hv_1[0] = fma2(Pr.x, aa1, hv_1[0]);
            hv_1[1] = fma2(Pr.y, aa1, hv_1[1]);
            hv_1[2] = fma2(Qr.x, aa1, hv_1[2]);
            hv_1[3] = fma2(Qr.y, aa1, hv_1[3]);
            hv_2[0] = fma2(P.x,  acac2, hv_2[0]);
            hv_2[1] = fma2(P.y,  acac2, hv_2[1]);
            hv_2[2] = fma2(Q2.x, acac2, hv_2[2]);
            hv_2[3] = fma2(Q2.y, acac2, hv_2[3]);
            hv_2[0] = fma2(Pq.x, cc2, hv_2[0]);
            hv_2[1] = fma2(Pq.y, cc2, hv_2[1]);
            hv_2[2] = fma2(Qq.x, cc2, hv_2[2]);
            hv_2[3] = fma2(Qq.y, cc2, hv_2[3]);
            hv_2[0] = fma2(Pr.x, aa2, hv_2[0]);
            hv_2[1] = fma2(Pr.y, aa2, hv_2[1]);
            hv_2[2] = fma2(Qr.x, aa2, hv_2[2]);
            hv_2[3] = fma2(Qr.y, aa2, hv_2[3]);
        }
    }

    // lin1_b
    float lb[8];
    {
        float4 lb0 = __ldg((const float4*)lin1_b);
        float4 lb1 = __ldg((const float4*)lin1_b + 1);
        lb[0]=lb0.x; lb[1]=lb0.y; lb[2]=lb0.z; lb[3]=lb0.w;
        lb[4]=lb1.x; lb[5]=lb1.y; lb[6]=lb1.z; lb[7]=lb1.w;
    }

    float hvf1[8], hvf2[8];
    #pragma unroll
    for (int j = 0; j < 4; j++) {
        float2 t1 = upk(hv_1[j]);
        float2 t2 = upk(hv_2[j]);
        hvf1[2*j] = t1.x + lb[2*j]; hvf1[2*j+1] = t1.y + lb[2*j+1];
        hvf2[2*j] = t2.x + lb[2*j]; hvf2[2*j+1] = t2.y + lb[2*j+1];
    }

    // ss = sum sE^2 (packed square-accumulate)
    u64 ssv1 = 0ull, ssv2 = 0ull;
    #pragma unroll
    for (int e = 0; e < 8; e++) {
        ssv1 = fma2(sE_1[e], sE_1[e], ssv1);
        ssv2 = fma2(sE_2[e], sE_2[e], ssv2);
    }
    float2 sp1 = upk(ssv1), sp2 = upk(ssv2);
    float2 fp1 = upk(ff_1), fp2 = upk(ff_2);
    float out1 = (fp1.x + fp1.y) * (1.0f / FDIM) + 0.5f * (sp1.x + sp1.y - q_1) * (1.0f / EDIM);
    float out2 = (fp2.x + fp2.y) * (1.0f / FDIM) + 0.5f * (sp2.x + sp2.y - q_2) * (1.0f / EDIM);
    out[i1] = out1;
    out[i2] = out2;

    float4* h1 = (float4*)g_h + (size_t)i1 * 2;
    float4* h2 = (float4*)g_h + (size_t)i2 * 2;
    h1[0] = make_float4(hvf1[0], hvf1[1], hvf1[2], hvf1[3]);
    h1[1] = make_float4(hvf1[4], hvf1[5], hvf1[6], hvf1[7]);
    h2[0] = make_float4(hvf2[0], hvf2[1], hvf2[2], hvf2[3]);
    h2[1] = make_float4(hvf2[4], hvf2[5], hvf2[6], hvf2[7]);

    // BN stats for both rows
    float st[16];
    #pragma unroll
    for (int j = 0; j < NH1; j++) {
        st[j]     = hvf1[j] + hvf2[j];
        st[8 + j] = hvf1[j] * hvf1[j] + hvf2[j] * hvf2[j];
    }
    #pragma unroll
    for (int off = 16; off; off >>= 1) {
        #pragma unroll
        for (int j = 0; j < 16; j++)
            st[j] += __shfl_xor_sync(0xffffffffu, st[j], off);
    }
    if ((tid & 31) == 0) {
        #pragma unroll
        for (int j = 0; j < 16; j++) atomicAdd(&sStat[j], st[j]);
    }
    __syncthreads();
    if (tid < 16) atomicAdd(&g_hstat[tid], sStat[tid]);
}

// ---------------- K4: BN finalize + fast tanh + lin2 ----------------
__device__ __forceinline__ float ftanh(float x) {
    float xx = fminf(fmaxf(x, -15.f), 15.f);
    float t = __expf(2.f * xx);
    return __fdividef(t - 1.f, t + 1.f);
}

__global__ void __launch_bounds__(256) k_deep(
    const float* __restrict__ gamma, const float* __restrict__ beta,
    const float* __restrict__ l2w, const float* __restrict__ l2b,
    float* __restrict__ out)
{
    int tid = threadIdx.x;
    int i = blockIdx.x * 256 + tid;
    // issue the heavy loads first (ptxas keeps LDG before BAR)
    const float4* h4 = (const float4*)g_h + (size_t)i * 2;
    float4 hA = h4[0];
    float4 hB = h4[1];
    float outv = out[i];

    __shared__ float fin[32];
    if (tid < NH1) {
        float mu  = g_hstat[tid] * (1.0f / NROWS);
        float var = g_hstat[NH1 + tid] * (1.0f / NROWS) - mu * mu;
        float rs  = rsqrtf(var + BN_EPS);
        float al  = gamma[tid] * rs;
        fin[tid] = al;
        fin[8 + tid] = beta[tid] - mu * al;
        float v = 0.f;
        #pragma unroll
        for (int j = 0; j < NH2; j++) v += l2w[j * NH1 + tid];
        fin[16 + tid] = v * (1.0f / NH2);
    }
    if (tid == 0) {
        float cb = 0.f;
        #pragma unroll
        for (int j = 0; j < NH2; j++) cb += l2b[j];
        fin[24] = cb * (1.0f / NH2);
    }
    __syncthreads();

    float hvv[8] = {hA.x, hA.y, hA.z, hA.w, hB.x, hB.y, hB.z, hB.w};
    float acc = fin[24];
    #pragma unroll
    for (int j = 0; j < NH1; j++)
        acc += fin[16 + j] * ftanh(fin[j] * hvv[j] + fin[8 + j]);
    out[i] = outv + acc;
}

extern "C" void kernel_launch(void* const* d_in, const int* in_sizes, int n_in,
                              void* d_out, int out_size)
{
    const float* Xa     = (const float*)d_in[0];
    const float* Xc     = (const float*)d_in[1];
    const float* w1     = (const float*)d_in[2];
    const float* b1     = (const float*)d_in[3];
    const float* w2     = (const float*)d_in[4];
    const float* b2     = (const float*)d_in[5];
    const float* W1     = (const float*)d_in[6];
    const float* B1     = (const float*)d_in[7];
    const float* W2     = (const float*)d_in[8];
    const float* B2     = (const float*)d_in[9];
    const float* L1w    = (const float*)d_in[10];
    const float* L1b    = (const float*)d_in[11];
    const float* g1     = (const float*)d_in[12];
    const float* be1    = (const float*)d_in[13];
    const float* L2w    = (const float*)d_in[14];
    const float* L2b    = (const float*)d_in[15];
    float* out = (float*)d_out;

    k_xcsum<<<NPART, 256>>>(Xc);
    k_setup<<<1, 256>>>(w2, b2, W1, W2, B1, B2, L1w);
    k_main<<<HROWS / 256, 256>>>(Xa, Xc, w1, b1, L1b, out);
    k_deep<<<NROWS / 256, 256>>>(g1, be1, L2w, L2b, out);
}

// round 6
// speedup vs baseline: 1.9241x; 1.0977x over previous
#include <cuda_runtime.h>

#define NROWS 65536
#define FDIM  64
#define EDIM  16
#define NH1   8
#define NH2   4
#define BN_EPS 1e-5f
#define NCTA  128
#define NTHR  256
#define HROWS (NROWS / 2)
#define ROWS_A (NROWS / NCTA)   /* 512 rows per CTA in phase A */

typedef unsigned long long u64;

// ---- device scratch ----
__device__ float g_part[NCTA * FDIM];
__device__ float g_hstat[2 * NH1];
__device__ unsigned g_cnt0 = 0, g_cnt1 = 0;
__device__ unsigned g_gen0 = 0, g_gen1 = 0;

// ---- f32x2 helpers ----
__device__ __forceinline__ u64 pk2(float x, float y) {
    u64 r; asm("mov.b64 %0, {%1,%2};" : "=l"(r) : "f"(x), "f"(y)); return r;
}
__device__ __forceinline__ u64 fma2(u64 a, u64 b, u64 c) {
    u64 d; asm("fma.rn.f32x2 %0, %1, %2, %3;" : "=l"(d) : "l"(a), "l"(b), "l"(c)); return d;
}
__device__ __forceinline__ u64 mul2(u64 a, u64 b) {
    u64 d; asm("mul.rn.f32x2 %0, %1, %2;" : "=l"(d) : "l"(a), "l"(b)); return d;
}
__device__ __forceinline__ float2 upk(u64 v) {
    float2 r; asm("mov.b64 {%0,%1}, %2;" : "=f"(r.x), "=f"(r.y) : "l"(v)); return r;
}

// ---- deadlock-free grid barrier: all NCTA CTAs are resident (NCTA <= 148) ----
__device__ __forceinline__ void grid_bar(unsigned* cnt, unsigned* gen) {
    __syncthreads();
    if (threadIdx.x == 0) {
        volatile unsigned* vg = (volatile unsigned*)gen;
        unsigned my = *vg;
        __threadfence();
        if (atomicAdd(cnt, 1) == NCTA - 1) {
            *cnt = 0;
            __threadfence();
            *vg = my + 1;
        } else {
            while (*vg == my) __nanosleep(64);
        }
    }
    __syncthreads();
    __threadfence();
}

__device__ __forceinline__ float ftanh(float x) {
    float xx = fminf(fmaxf(x, -15.f), 15.f);
    float t = __expf(2.f * xx);
    return __fdividef(t - 1.f, t + 1.f);
}

__global__ void __launch_bounds__(NTHR) k_all(
    const float* __restrict__ Xa, const float* __restrict__ Xc,
    const float* __restrict__ w1, const float* __restrict__ b1,
    const float* __restrict__ w2, const float* __restrict__ b2,
    const float* __restrict__ W1, const float* __restrict__ B1,
    const float* __restrict__ W2, const float* __restrict__ B2,
    const float* __restrict__ L1w, const float* __restrict__ L1b,
    const float* __restrict__ gam, const float* __restrict__ bet,
    const float* __restrict__ L2w, const float* __restrict__ L2b,
    float* __restrict__ out)
{
    __shared__ ulonglong2 sS[FDIM * 12];   // per f: U[4 x ull2], B1[4], B2[4]
    __shared__ float      sMhF[FDIM * 24]; // per f: P[8],Q[8],R[8]
    __shared__ u64        sC[FDIM * 10];   // per f dup-pairs: w1,b1,k,m0,m1,m2,2m3,2m4,2m5,pad
    __shared__ float4     spA[NTHR];
    __shared__ float      sRed[4 * FDIM];
    __shared__ float      sXc[FDIM];
    __shared__ float      sStat[16];
    __shared__ float      sFin[32];

    int tid = threadIdx.x;
    int cta = blockIdx.x;

    // ================= Phase A: Xc column partial sums =================
    {
        int f4 = tid & 15, rg = tid >> 4;
        const float4* Xc4 = (const float4*)Xc;
        float4 acc = make_float4(0.f, 0.f, 0.f, 0.f);
        size_t r = (size_t)cta * ROWS_A + rg;
        #pragma unroll 4
        for (int it = 0; it < ROWS_A / 16; it++, r += 16) {
            float4 v = Xc4[r * 16 + f4];
            acc.x += v.x; acc.y += v.y; acc.z += v.z; acc.w += v.w;
        }
        spA[tid] = acc;
        __syncthreads();
        if (tid < 16) {
            float4 t = make_float4(0.f, 0.f, 0.f, 0.f);
            #pragma unroll
            for (int g = 0; g < 16; g++) {
                float4 v = spA[g * 16 + tid];
                t.x += v.x; t.y += v.y; t.z += v.z; t.w += v.w;
            }
            ((float4*)g_part)[cta * 16 + tid] = t;
        }
        if (cta == 0 && tid < 16) g_hstat[tid] = 0.f;
    }
    grid_bar(&g_cnt0, &g_gen0);

    // ================= Phase B: constants (each CTA redundantly, into smem) ======
    {
        int col = tid & 63, grp = tid >> 6;
        float acc = 0.f;
        #pragma unroll 8
        for (int p = grp; p < NCTA; p += 4)
            acc += __ldcg(&g_part[p * FDIM + col]);
        sRed[grp * FDIM + col] = acc;
    }
    __syncthreads();
    if (tid < FDIM)
        sXc[tid] = sRed[tid] + sRed[FDIM + tid] + sRed[2 * FDIM + tid] + sRed[3 * FDIM + tid];
    {
        // fill sS: tid covers all FDIM*4 = 256 float4 slots
        int f = tid >> 2, j = tid & 3;
        float4 w1v = ((const float4*)W1)[tid];
        float4 w2v = ((const float4*)W2)[tid];
        float4 u = make_float4(w1v.x + w2v.x, w1v.y + w2v.y, w1v.z + w2v.z, w1v.w + w2v.w);
        float4* sSf = (float4*)sS;
        sSf[f * 12 + j]     = u;
        sSf[f * 12 + 4 + j] = ((const float4*)B1)[tid];
        sSf[f * 12 + 8 + j] = ((const float4*)B2)[tid];
    }
    if (tid < 16) sStat[tid] = 0.f;
    __syncthreads();
    if (tid < FDIM) {
        int f = tid;
        const float* Uf  = (const float*)&sS[f * 12];
        const float* B1f = Uf + 16;
        const float* B2f = Uf + 32;
        float m0 = 0, m1 = 0, m2 = 0, m3 = 0, m4 = 0, m5 = 0;
        #pragma unroll
        for (int e = 0; e < EDIM; e++) {
            float u = Uf[e], x = B1f[e], y = B2f[e];
            m0 += u * u; m1 += x * x; m2 += y * y;
            m3 += u * x; m4 += u * y; m5 += x * y;
        }
        float xcm = sXc[f] * (1.0f / NROWS);
        float kf = w2[f] * xcm + b2[f];
        float w1f = w1[f], b1f = b1[f];
        sC[f * 10 + 0] = pk2(w1f, w1f);
        sC[f * 10 + 1] = pk2(b1f, b1f);
        sC[f * 10 + 2] = pk2(kf, kf);
        sC[f * 10 + 3] = pk2(m0, m0);
        sC[f * 10 + 4] = pk2(m1, m1);
        sC[f * 10 + 5] = pk2(m2, m2);
        sC[f * 10 + 6] = pk2(2.f * m3, 2.f * m3);
        sC[f * 10 + 7] = pk2(2.f * m4, 2.f * m4);
        sC[f * 10 + 8] = pk2(2.f * m5, 2.f * m5);
        sC[f * 10 + 9] = 0ull;
    }
    #pragma unroll
    for (int idx = tid; idx < FDIM * NH1; idx += NTHR) {
        int f = idx >> 3, j = idx & 7;
        const float* lr  = L1w + j * (FDIM * EDIM) + f * EDIM;
        const float* Uf  = (const float*)&sS[f * 12];
        const float* B1f = Uf + 16;
        const float* B2f = Uf + 32;
        float P = 0, Q = 0, R = 0;
        #pragma unroll
        for (int e = 0; e < EDIM; e++) {
            float l = lr[e];
            P += Uf[e] * l; Q += B1f[e] * l; R += B2f[e] * l;
        }
        sMhF[f * 24 + j]      = P;
        sMhF[f * 24 + 8 + j]  = Q;
        sMhF[f * 24 + 16 + j] = R;
    }
    __syncthreads();

    // ================= Phase C: main per-row pass (2 rows/thread) =================
    int i1 = cta * NTHR + tid;
    int i2 = i1 + HROWS;
    const float4* A1 = (const float4*)Xa + (size_t)i1 * 16;
    const float4* C1 = (const float4*)Xc + (size_t)i1 * 16;
    const float4* A2 = (const float4*)Xa + (size_t)i2 * 16;
    const float4* C2 = (const float4*)Xc + (size_t)i2 * 16;

    u64 sE_1[8], sE_2[8], hv_1[4], hv_2[4];
    u64 ff12 = 0ull, q12 = 0ull;
    #pragma unroll
    for (int e = 0; e < 8; e++) { sE_1[e] = 0ull; sE_2[e] = 0ull; }
    #pragma unroll
    for (int j = 0; j < 4; j++) { hv_1[j] = 0ull; hv_2[j] = 0ull; }

    #pragma unroll 2
    for (int ch = 0; ch < 16; ch++) {
        float4 a41 = A1[ch], c41 = C1[ch];
        float4 a42 = A2[ch], c42 = C2[ch];
        float av1[4] = {a41.x, a41.y, a41.z, a41.w};
        float cv1[4] = {c41.x, c41.y, c41.z, c41.w};
        float av2[4] = {a42.x, a42.y, a42.z, a42.w};
        float cv2[4] = {c42.x, c42.y, c42.z, c42.w};
        #pragma unroll
        for (int u = 0; u < 4; u++) {
            int f = ch * 4 + u;
            float a1 = av1[u], c1v = cv1[u];
            float a2 = av2[u], c2v = cv2[u];
            float ac1 = a1 * c1v, ac2 = a2 * c2v;
            u64 A12 = pk2(a1, a2), C12 = pk2(c1v, c2v), AC12 = pk2(ac1, ac2);

            // ff + quad (dual-row packed, dup'd constants)
            const ulonglong2* cp = (const ulonglong2*)&sC[f * 10];
            ulonglong2 cA = cp[0];  // w1d, b1d
            ulonglong2 cB = cp[1];  // kd, m0d
            ulonglong2 cC = cp[2];  // m1d, m2d
            ulonglong2 cD = cp[3];  // m3d2, m4d2
            u64 m5d = sC[f * 10 + 8];
            ff12 = fma2(AC12, cA.x, ff12);
            ff12 = fma2(C12,  cA.y, ff12);
            ff12 = fma2(A12,  cB.x, ff12);
            q12 = fma2(mul2(AC12, AC12), cB.y, q12);
            q12 = fma2(mul2(C12, C12),   cC.x, q12);
            q12 = fma2(mul2(A12, A12),   cC.y, q12);
            q12 = fma2(mul2(AC12, C12),  cD.x, q12);
            q12 = fma2(mul2(AC12, A12),  cD.y, q12);
            q12 = fma2(AC12, m5d, q12);

            u64 aa1 = pk2(a1, a1), cc1 = pk2(c1v, c1v), acac1 = pk2(ac1, ac1);
            u64 aa2 = pk2(a2, a2), cc2 = pk2(c2v, c2v), acac2 = pk2(ac2, ac2);

            // s[e] matvec (constants shared by both rows)
            const ulonglong2* sp = &sS[f * 12];
            #pragma unroll
            for (int g = 0; g < 4; g++) {
                ulonglong2 uu  = sp[g];
                ulonglong2 bb1 = sp[4 + g];
                ulonglong2 bb2 = sp[8 + g];
                sE_1[2*g]   = fma2(uu.x, acac1, sE_1[2*g]);
                sE_1[2*g+1] = fma2(uu.y, acac1, sE_1[2*g+1]);
                sE_2[2*g]   = fma2(uu.x, acac2, sE_2[2*g]);
                sE_2[2*g+1] = fma2(uu.y, acac2, sE_2[2*g+1]);
                sE_1[2*g]   = fma2(bb1.x, cc1, sE_1[2*g]);
                sE_1[2*g+1] = fma2(bb1.y, cc1, sE_1[2*g+1]);
                sE_2[2*g]   = fma2(bb1.x, cc2, sE_2[2*g]);
                sE_2[2*g+1] = fma2(bb1.y, cc2, sE_2[2*g+1]);
                sE_1[2*g]   = fma2(bb2.x, aa1, sE_1[2*g]);
                sE_1[2*g+1] = fma2(bb2.y, aa1, sE_1[2*g+1]);
                sE_2[2*g]   = fma2(bb2.x, aa2, sE_2[2*g]);
                sE_2[2*g+1] = fma2(bb2.y, aa2, sE_2[2*g+1]);
            }
            // h matvec
            const ulonglong2* mh = (const ulonglong2*)&sMhF[f * 24];
            ulonglong2 P = mh[0], P2 = mh[1];
            ulonglong2 Qm = mh[2], Q2 = mh[3];
            ulonglong2 R = mh[4], R2 = mh[5];
            hv_1[0] = fma2(P.x,  acac1, hv_1[0]);
            hv_1[1] = fma2(P.y,  acac1, hv_1[1]);
            hv_1[2] = fma2(P2.x, acac1, hv_1[2]);
            hv_1[3] = fma2(P2.y, acac1, hv_1[3]);
            hv_1[0] = fma2(Qm.x, cc1, hv_1[0]);
            hv_1[1] = fma2(Qm.y, cc1, hv_1[1]);
            hv_1[2] = fma2(Q2.x, cc1, hv_1[2]);
            hv_1[3] = fma2(Q2.y, cc1, hv_1[3]);
            hv_1[0] = fma2(R.x,  aa1, hv_1[0]);
            hv_1[1] = fma2(R.y,  aa1, hv_1[1]);
            hv_1[2] = fma2(R2.x, aa1, hv_1[2]);
            hv_1[3] = fma2(R2.y, aa1, hv_1[3]);
            hv_2[0] = fma2(P.x,  acac2, hv_2[0]);
            hv_2[1] = fma2(P.y,  acac2, hv_2[1]);
            hv_2[2] = fma2(P2.x, acac2, hv_2[2]);
            hv_2[3] = fma2(P2.y, acac2, hv_2[3]);
            hv_2[0] = fma2(Qm.x, cc2, hv_2[0]);
            hv_2[1] = fma2(Qm.y, cc2, hv_2[1]);
            hv_2[2] = fma2(Q2.x, cc2, hv_2[2]);
            hv_2[3] = fma2(Q2.y, cc2, hv_2[3]);
            hv_2[0] = fma2(R.x,  aa2, hv_2[0]);
            hv_2[1] = fma2(R.y,  aa2, hv_2[1]);
            hv_2[2] = fma2(R2.x, aa2, hv_2[2]);
            hv_2[3] = fma2(R2.y, aa2, hv_2[3]);
        }
    }

    // finalize fm parts
    u64 ssv1 = 0ull, ssv2 = 0ull;
    #pragma unroll
    for (int e = 0; e < 8; e++) {
        ssv1 = fma2(sE_1[e], sE_1[e], ssv1);
        ssv2 = fma2(sE_2[e], sE_2[e], ssv2);
    }
    float2 sp1 = upk(ssv1), sp2 = upk(ssv2);
    float2 fp = upk(ff12), qp = upk(q12);
    float out1 = fp.x * (1.0f / FDIM) + 0.5f * (sp1.x + sp1.y - qp.x) * (1.0f / EDIM);
    float out2 = fp.y * (1.0f / FDIM) + 0.5f * (sp2.x + sp2.y - qp.y) * (1.0f / EDIM);

    // h with lin1_b
    float lb[8];
    {
        float4 lb0 = __ldg((const float4*)L1b);
        float4 lb1 = __ldg((const float4*)L1b + 1);
        lb[0]=lb0.x; lb[1]=lb0.y; lb[2]=lb0.z; lb[3]=lb0.w;
        lb[4]=lb1.x; lb[5]=lb1.y; lb[6]=lb1.z; lb[7]=lb1.w;
    }
    float hvf1[8], hvf2[8];
    #pragma unroll
    for (int j = 0; j < 4; j++) {
        float2 t1 = upk(hv_1[j]);
        float2 t2 = upk(hv_2[j]);
        hvf1[2*j] = t1.x + lb[2*j]; hvf1[2*j+1] = t1.y + lb[2*j+1];
        hvf2[2*j] = t2.x + lb[2*j]; hvf2[2*j+1] = t2.y + lb[2*j+1];
    }

    // BN stats
    {
        float st[16];
        #pragma unroll
        for (int j = 0; j < NH1; j++) {
            st[j]     = hvf1[j] + hvf2[j];
            st[8 + j] = hvf1[j] * hvf1[j] + hvf2[j] * hvf2[j];
        }
        #pragma unroll
        for (int off = 16; off; off >>= 1) {
            #pragma unroll
            for (int j = 0; j < 16; j++)
                st[j] += __shfl_xor_sync(0xffffffffu, st[j], off);
        }
        if ((tid & 31) == 0) {
            #pragma unroll
            for (int j = 0; j < 16; j++) atomicAdd(&sStat[j], st[j]);
        }
        __syncthreads();
        if (tid < 16) atomicAdd(&g_hstat[tid], sStat[tid]);
    }
    grid_bar(&g_cnt1, &g_gen1);

    // ================= Phase D: BN finalize + tanh + lin2 + store =================
    if (tid < NH1) {
        float sh = __ldcg(&g_hstat[tid]);
        float sq = __ldcg(&g_hstat[NH1 + tid]);
        float mu  = sh * (1.0f / NROWS);
        float var = sq * (1.0f / NROWS) - mu * mu;
        float rs  = rsqrtf(var + BN_EPS);
        float al  = gam[tid] * rs;
        sFin[tid] = al;
        sFin[8 + tid] = bet[tid] - mu * al;
        float v = 0.f;
        #pragma unroll
        for (int j = 0; j < NH2; j++) v += L2w[j * NH1 + tid];
        sFin[16 + tid] = v * (1.0f / NH2);
    }
    if (tid == 0) {
        float cb = 0.f;
        #pragma unroll
        for (int j = 0; j < NH2; j++) cb += L2b[j];
        sFin[24] = cb * (1.0f / NH2);
    }
    __syncthreads();

    float acc1 = sFin[24], acc2 = sFin[24];
    #pragma unroll
    for (int j = 0; j < NH1; j++) {
        float al = sFin[j], bp = sFin[8 + j], vv = sFin[16 + j];
        acc1 += vv * ftanh(al * hvf1[j] + bp);
        acc2 += vv * ftanh(al * hvf2[j] + bp);
    }
    out[i1] = out1 + acc1;
    out[i2] = out2 + acc2;
}

extern "C" void kernel_launch(void* const* d_in, const int* in_sizes, int n_in,
                              void* d_out, int out_size)
{
    const float* Xa  = (const float*)d_in[0];
    const float* Xc  = (const float*)d_in[1];
    const float* w1  = (const float*)d_in[2];
    const float* b1  = (const float*)d_in[3];
    const float* w2  = (const float*)d_in[4];
    const float* b2  = (const float*)d_in[5];
    const float* W1  = (const float*)d_in[6];
    const float* B1  = (const float*)d_in[7];
    const float* W2  = (const float*)d_in[8];
    const float* B2  = (const float*)d_in[9];
    const float* L1w = (const float*)d_in[10];
    const float* L1b = (const float*)d_in[11];
    const float* g1  = (const float*)d_in[12];
    const float* be1 = (const float*)d_in[13];
    const float* L2w = (const float*)d_in[14];
    const float* L2b = (const float*)d_in[15];
    float* out = (float*)d_out;

    k_all<<<NCTA, NTHR>>>(Xa, Xc, w1, b1, w2, b2, W1, B1, W2, B2,
                          L1w, L1b, g1, be1, L2w, L2b, out);
}

// round 7
// speedup vs baseline: 2.0272x; 1.0536x over previous
#include <cuda_runtime.h>

#define NROWS 65536
#define FDIM  64
#define EDIM  16
#define NH1   8
#define NH2   4
#define BN_EPS 1e-5f
#define NCTA  128
#define NTHR  128
#define QROWS (NROWS / 4)        /* 16384: stride between a thread's 4 rows */
#define ROWS_A (NROWS / NCTA)    /* 512 rows per CTA in phase A */

typedef unsigned long long u64;

// ---- device scratch ----
__device__ float g_part[NCTA * FDIM];
__device__ float g_hstat[2 * NH1];
__device__ unsigned g_cnt0 = 0, g_cnt1 = 0;
__device__ unsigned g_gen0 = 0, g_gen1 = 0;

// ---- f32x2 helpers ----
__device__ __forceinline__ u64 pk2(float x, float y) {
    u64 r; asm("mov.b64 %0, {%1,%2};" : "=l"(r) : "f"(x), "f"(y)); return r;
}
__device__ __forceinline__ u64 fma2(u64 a, u64 b, u64 c) {
    u64 d; asm("fma.rn.f32x2 %0, %1, %2, %3;" : "=l"(d) : "l"(a), "l"(b), "l"(c)); return d;
}
__device__ __forceinline__ u64 mul2(u64 a, u64 b) {
    u64 d; asm("mul.rn.f32x2 %0, %1, %2;" : "=l"(d) : "l"(a), "l"(b)); return d;
}
__device__ __forceinline__ float2 upk(u64 v) {
    float2 r; asm("mov.b64 {%0,%1}, %2;" : "=f"(r.x), "=f"(r.y) : "l"(v)); return r;
}

// ---- deadlock-free grid barrier (all NCTA CTAs resident; NCTA <= 148) ----
__device__ __forceinline__ void grid_bar(unsigned* cnt, unsigned* gen) {
    __syncthreads();
    if (threadIdx.x == 0) {
        volatile unsigned* vg = (volatile unsigned*)gen;
        unsigned my = *vg;
        __threadfence();
        if (atomicAdd(cnt, 1) == NCTA - 1) {
            *cnt = 0;
            __threadfence();
            *vg = my + 1;
        } else {
            while (*vg == my) __nanosleep(64);
        }
    }
    __syncthreads();
    __threadfence();
}

__device__ __forceinline__ float ftanh(float x) {
    float xx = fminf(fmaxf(x, -15.f), 15.f);
    float t = __expf(2.f * xx);
    return __fdividef(t - 1.f, t + 1.f);
}

__global__ void __launch_bounds__(NTHR) k_all(
    const float* __restrict__ Xa, const float* __restrict__ Xc,
    const float* __restrict__ w1, const float* __restrict__ b1,
    const float* __restrict__ w2, const float* __restrict__ b2,
    const float* __restrict__ W1, const float* __restrict__ B1,
    const float* __restrict__ W2, const float* __restrict__ B2,
    const float* __restrict__ L1w, const float* __restrict__ L1b,
    const float* __restrict__ gam, const float* __restrict__ bet,
    const float* __restrict__ L2w, const float* __restrict__ L2b,
    float* __restrict__ out)
{
    __shared__ ulonglong2 sS[FDIM * 12];   // per f: U[4 ull2], B1[4], B2[4]
    __shared__ float      sMhF[FDIM * 24]; // per f: P[8],Q[8],R[8]
    __shared__ float      sCf[FDIM * 12];  // per f: w1',b1',k',m0',m1',m2',m3',m4',m5',pad3 (pre-scaled)
    __shared__ float4     spA[NTHR];
    __shared__ float      sRed[2 * FDIM];
    __shared__ float      sXc[FDIM];
    __shared__ float      sStat[16];
    __shared__ float      sFin[32];

    int tid = threadIdx.x;
    int cta = blockIdx.x;

    // ================= Phase A: Xc column partial sums =================
    {
        int f4 = tid & 15, rg = tid >> 4;          // 16 quads x 8 row-groups
        const float4* Xc4 = (const float4*)Xc;
        float4 acc = make_float4(0.f, 0.f, 0.f, 0.f);
        size_t r = (size_t)cta * ROWS_A + rg;
        #pragma unroll 8
        for (int it = 0; it < ROWS_A / 8; it++, r += 8) {
            float4 v = Xc4[r * 16 + f4];
            acc.x += v.x; acc.y += v.y; acc.z += v.z; acc.w += v.w;
        }
        spA[tid] = acc;
        __syncthreads();
        if (tid < 16) {
            float4 t = make_float4(0.f, 0.f, 0.f, 0.f);
            #pragma unroll
            for (int g = 0; g < 8; g++) {
                float4 v = spA[g * 16 + tid];
                t.x += v.x; t.y += v.y; t.z += v.z; t.w += v.w;
            }
            ((float4*)g_part)[cta * 16 + tid] = t;
        }
        if (cta == 0 && tid < 16) g_hstat[tid] = 0.f;
    }
    grid_bar(&g_cnt0, &g_gen0);

    // ================= Phase B: constants (each CTA redundantly) =================
    {
        int col = tid & 63, grp = tid >> 6;        // 2 groups of 64
        float acc = 0.f;
        #pragma unroll 8
        for (int p = grp; p < NCTA; p += 2)
            acc += __ldcg(&g_part[p * FDIM + col]);
        sRed[grp * FDIM + col] = acc;
    }
    {
        // fill sS: FDIM*4 = 256 float4 slots, 128 threads -> 2 iters
        float4* sSf = (float4*)sS;
        #pragma unroll
        for (int idx = tid; idx < FDIM * 4; idx += NTHR) {
            int f = idx >> 2, j = idx & 3;
            float4 w1v = ((const float4*)W1)[idx];
            float4 w2v = ((const float4*)W2)[idx];
            sSf[f * 12 + j] = make_float4(w1v.x + w2v.x, w1v.y + w2v.y,
                                          w1v.z + w2v.z, w1v.w + w2v.w);
            sSf[f * 12 + 4 + j] = ((const float4*)B1)[idx];
            sSf[f * 12 + 8 + j] = ((const float4*)B2)[idx];
        }
    }
    if (tid < 16) sStat[tid] = 0.f;
    __syncthreads();
    if (tid < FDIM) sXc[tid] = sRed[tid] + sRed[FDIM + tid];
    __syncthreads();
    if (tid < FDIM) {
        int f = tid;
        const float* Uf  = (const float*)&sS[f * 12];
        const float* B1f = Uf + 16;
        const float* B2f = Uf + 32;
        float m0 = 0, m1 = 0, m2 = 0, m3 = 0, m4 = 0, m5 = 0;
        #pragma unroll
        for (int e = 0; e < EDIM; e++) {
            float u = Uf[e], x = B1f[e], y = B2f[e];
            m0 += u * u; m1 += x * x; m2 += y * y;
            m3 += u * x; m4 += u * y; m5 += x * y;
        }
        float xcm = sXc[f] * (1.0f / NROWS);
        float kf = w2[f] * xcm + b2[f];
        const float sF = 1.0f / FDIM;     // ff scale
        const float sQ = 1.0f / 32.0f;    // 0.5/EDIM
        sCf[f * 12 + 0] = w1[f] * sF;
        sCf[f * 12 + 1] = b1[f] * sF;
        sCf[f * 12 + 2] = kf * sF;
        sCf[f * 12 + 3] = m0 * sQ;
        sCf[f * 12 + 4] = m1 * sQ;
        sCf[f * 12 + 5] = m2 * sQ;
        sCf[f * 12 + 6] = 2.f * m3 * sQ;
        sCf[f * 12 + 7] = 2.f * m4 * sQ;
        sCf[f * 12 + 8] = 2.f * m5 * sQ;
        sCf[f * 12 + 9] = 0.f; sCf[f * 12 + 10] = 0.f; sCf[f * 12 + 11] = 0.f;
    }
    #pragma unroll
    for (int idx = tid; idx < FDIM * NH1; idx += NTHR) {
        int f = idx >> 3, j = idx & 7;
        const float* lr  = L1w + j * (FDIM * EDIM) + f * EDIM;
        const float* Uf  = (const float*)&sS[f * 12];
        const float* B1f = Uf + 16;
        const float* B2f = Uf + 32;
        float P = 0, Q = 0, R = 0;
        #pragma unroll
        for (int e = 0; e < EDIM; e++) {
            float l = lr[e];
            P += Uf[e] * l; Q += B1f[e] * l; R += B2f[e] * l;
        }
        sMhF[f * 24 + j]      = P;
        sMhF[f * 24 + 8 + j]  = Q;
        sMhF[f * 24 + 16 + j] = R;
    }
    __syncthreads();

    // ================= Phase C: main pass, 4 rows per thread =================
    int base = cta * NTHR + tid;                    // 0..16383
    const float4* Ap[4];
    const float4* Cp[4];
    #pragma unroll
    for (int r = 0; r < 4; r++) {
        Ap[r] = (const float4*)Xa + ((size_t)base + (size_t)r * QROWS) * 16;
        Cp[r] = (const float4*)Xc + ((size_t)base + (size_t)r * QROWS) * 16;
    }

    u64 sE[4][8], hv[4][4];
    u64 ff01 = 0ull, ff23 = 0ull, q01 = 0ull, q23 = 0ull;
    #pragma unroll
    for (int r = 0; r < 4; r++) {
        #pragma unroll
        for (int g = 0; g < 8; g++) sE[r][g] = 0ull;
        #pragma unroll
        for (int j = 0; j < 4; j++) hv[r][j] = 0ull;
    }

    float4 a4c[4], c4c[4];
    #pragma unroll
    for (int r = 0; r < 4; r++) { a4c[r] = Ap[r][0]; c4c[r] = Cp[r][0]; }

    #pragma unroll 2
    for (int ch = 0; ch < 16; ch++) {
        float4 a4n[4], c4n[4];
        if (ch < 15) {
            #pragma unroll
            for (int r = 0; r < 4; r++) { a4n[r] = Ap[r][ch + 1]; c4n[r] = Cp[r][ch + 1]; }
        }
        float Af[4][4], Cf[4][4];
        #pragma unroll
        for (int r = 0; r < 4; r++) {
            Af[r][0] = a4c[r].x; Af[r][1] = a4c[r].y; Af[r][2] = a4c[r].z; Af[r][3] = a4c[r].w;
            Cf[r][0] = c4c[r].x; Cf[r][1] = c4c[r].y; Cf[r][2] = c4c[r].z; Cf[r][3] = c4c[r].w;
        }
        #pragma unroll
        for (int u = 0; u < 4; u++) {
            int f = ch * 4 + u;
            float a_[4], c_[4], ac_[4];
            #pragma unroll
            for (int r = 0; r < 4; r++) {
                a_[r] = Af[r][u]; c_[r] = Cf[r][u]; ac_[r] = a_[r] * c_[r];
            }
            u64 A01 = pk2(a_[0], a_[1]), A23 = pk2(a_[2], a_[3]);
            u64 C01 = pk2(c_[0], c_[1]), C23 = pk2(c_[2], c_[3]);
            u64 AC01 = pk2(ac_[0], ac_[1]), AC23 = pk2(ac_[2], ac_[3]);

            // ff + quad (packed over row-pairs, scalar consts dup'd via mov)
            const float4* cf = (const float4*)&sCf[f * 12];
            float4 k0 = cf[0], k1 = cf[1], k2v = cf[2];
            u64 w1d = pk2(k0.x, k0.x), b1d = pk2(k0.y, k0.y), kd = pk2(k0.z, k0.z);
            u64 m0d = pk2(k0.w, k0.w), m1d = pk2(k1.x, k1.x), m2d = pk2(k1.y, k1.y);
            u64 m3d = pk2(k1.z, k1.z), m4d = pk2(k1.w, k1.w), m5d = pk2(k2v.x, k2v.x);

            ff01 = fma2(AC01, w1d, ff01); ff01 = fma2(C01, b1d, ff01); ff01 = fma2(A01, kd, ff01);
            ff23 = fma2(AC23, w1d, ff23); ff23 = fma2(C23, b1d, ff23); ff23 = fma2(A23, kd, ff23);
            q01 = fma2(mul2(AC01, AC01), m0d, q01);
            q01 = fma2(mul2(C01, C01),   m1d, q01);
            q01 = fma2(mul2(A01, A01),   m2d, q01);
            q01 = fma2(mul2(AC01, C01),  m3d, q01);
            q01 = fma2(mul2(AC01, A01),  m4d, q01);
            q01 = fma2(AC01, m5d, q01);
            q23 = fma2(mul2(AC23, AC23), m0d, q23);
            q23 = fma2(mul2(C23, C23),   m1d, q23);
            q23 = fma2(mul2(A23, A23),   m2d, q23);
            q23 = fma2(mul2(AC23, C23),  m3d, q23);
            q23 = fma2(mul2(AC23, A23),  m4d, q23);
            q23 = fma2(AC23, m5d, q23);

            u64 aa[4], cc[4], acac[4];
            #pragma unroll
            for (int r = 0; r < 4; r++) {
                aa[r] = pk2(a_[r], a_[r]);
                cc[r] = pk2(c_[r], c_[r]);
                acac[r] = pk2(ac_[r], ac_[r]);
            }

            // s[e] matvec — 12 LDS.128 serve all 4 rows
            const ulonglong2* sp = &sS[f * 12];
            #pragma unroll
            for (int g = 0; g < 4; g++) {
                ulonglong2 uu  = sp[g];
                ulonglong2 bb1 = sp[4 + g];
                ulonglong2 bb2 = sp[8 + g];
                #pragma unroll
                for (int r = 0; r < 4; r++) {
                    sE[r][2*g]   = fma2(uu.x,  acac[r], sE[r][2*g]);
                    sE[r][2*g+1] = fma2(uu.y,  acac[r], sE[r][2*g+1]);
                    sE[r][2*g]   = fma2(bb1.x, cc[r],   sE[r][2*g]);
                    sE[r][2*g+1] = fma2(bb1.y, cc[r],   sE[r][2*g+1]);
                    sE[r][2*g]   = fma2(bb2.x, aa[r],   sE[r][2*g]);
                    sE[r][2*g+1] = fma2(bb2.y, aa[r],   sE[r][2*g+1]);
                }
            }
            // h matvec — 6 LDS.128 serve all 4 rows
            const ulonglong2* mh = (const ulonglong2*)&sMhF[f * 24];
            ulonglong2 P0 = mh[0], P1 = mh[1];
            ulonglong2 Q0 = mh[2], Q1 = mh[3];
            ulonglong2 R0 = mh[4], R1 = mh[5];
            #pragma unroll
            for (int r = 0; r < 4; r++) {
                hv[r][0] = fma2(P0.x, acac[r], hv[r][0]);
                hv[r][1] = fma2(P0.y, acac[r], hv[r][1]);
                hv[r][2] = fma2(P1.x, acac[r], hv[r][2]);
                hv[r][3] = fma2(P1.y, acac[r], hv[r][3]);
                hv[r][0] = fma2(Q0.x, cc[r], hv[r][0]);
                hv[r][1] = fma2(Q0.y, cc[r], hv[r][1]);
                hv[r][2] = fma2(Q1.x, cc[r], hv[r][2]);
                hv[r][3] = fma2(Q1.y, cc[r], hv[r][3]);
                hv[r][0] = fma2(R0.x, aa[r], hv[r][0]);
                hv[r][1] = fma2(R0.y, aa[r], hv[r][1]);
                hv[r][2] = fma2(R1.x, aa[r], hv[r][2]);
                hv[r][3] = fma2(R1.y, aa[r], hv[r][3]);
            }
        }
        if (ch < 15) {
            #pragma unroll
            for (int r = 0; r < 4; r++) { a4c[r] = a4n[r]; c4c[r] = c4n[r]; }
        }
    }

    // finalize fm parts:  out = ff' + ss/32 - q'
    float outv[4];
    {
        float2 fp01 = upk(ff01), fp23 = upk(ff23);
        float2 qp01 = upk(q01),  qp23 = upk(q23);
        float ffs[4] = {fp01.x, fp01.y, fp23.x, fp23.y};
        float qs[4]  = {qp01.x, qp01.y, qp23.x, qp23.y};
        #pragma unroll
        for (int r = 0; r < 4; r++) {
            u64 ssv = 0ull;
            #pragma unroll
            for (int g = 0; g < 8; g++) ssv = fma2(sE[r][g], sE[r][g], ssv);
            float2 sv = upk(ssv);
            outv[r] = ffs[r] + (sv.x + sv.y) * (1.0f / 32.0f) - qs[r];
        }
    }

    // h with lin1_b
    float lb[8];
    {
        float4 lb0 = __ldg((const float4*)L1b);
        float4 lb1 = __ldg((const float4*)L1b + 1);
        lb[0]=lb0.x; lb[1]=lb0.y; lb[2]=lb0.z; lb[3]=lb0.w;
        lb[4]=lb1.x; lb[5]=lb1.y; lb[6]=lb1.z; lb[7]=lb1.w;
    }
    float hvf[4][8];
    #pragma unroll
    for (int r = 0; r < 4; r++) {
        #pragma unroll
        for (int j = 0; j < 4; j++) {
            float2 t = upk(hv[r][j]);
            hvf[r][2*j]   = t.x + lb[2*j];
            hvf[r][2*j+1] = t.y + lb[2*j+1];
        }
    }

    // BN stats over 4 rows
    {
        float st[16];
        #pragma unroll
        for (int j = 0; j < NH1; j++) {
            float s = 0.f, sq = 0.f;
            #pragma unroll
            for (int r = 0; r < 4; r++) { s += hvf[r][j]; sq += hvf[r][j] * hvf[r][j]; }
            st[j] = s; st[8 + j] = sq;
        }
        #pragma unroll
        for (int off = 16; off; off >>= 1) {
            #pragma unroll
            for (int j = 0; j < 16; j++)
                st[j] += __shfl_xor_sync(0xffffffffu, st[j], off);
        }
        if ((tid & 31) == 0) {
            #pragma unroll
            for (int j = 0; j < 16; j++) atomicAdd(&sStat[j], st[j]);
        }
        __syncthreads();
        if (tid < 16) atomicAdd(&g_hstat[tid], sStat[tid]);
    }
    grid_bar(&g_cnt1, &g_gen1);

    // ================= Phase D: BN finalize + tanh + lin2 + store =================
    if (tid < NH1) {
        float sh = __ldcg(&g_hstat[tid]);
        float sq = __ldcg(&g_hstat[NH1 + tid]);
        float mu  = sh * (1.0f / NROWS);
        float var = sq * (1.0f / NROWS) - mu * mu;
        float rs  = rsqrtf(var + BN_EPS);
        float al  = gam[tid] * rs;
        sFin[tid] = al;
        sFin[8 + tid] = bet[tid] - mu * al;
        float v = 0.f;
        #pragma unroll
        for (int j = 0; j < NH2; j++) v += L2w[j * NH1 + tid];
        sFin[16 + tid] = v * (1.0f / NH2);
    }
    if (tid == 0) {
        float cb = 0.f;
        #pragma unroll
        for (int j = 0; j < NH2; j++) cb += L2b[j];
        sFin[24] = cb * (1.0f / NH2);
    }
    __syncthreads();

    #pragma unroll
    for (int r = 0; r < 4; r++) {
        float acc = sFin[24];
        #pragma unroll
        for (int j = 0; j < NH1; j++)
            acc += sFin[16 + j] * ftanh(sFin[j] * hvf[r][j] + sFin[8 + j]);
        out[base + r * QROWS] = outv[r] + acc;
    }
}

extern "C" void kernel_launch(void* const* d_in, const int* in_sizes, int n_in,
                              void* d_out, int out_size)
{
    const float* Xa  = (const float*)d_in[0];
    const float* Xc  = (const float*)d_in[1];
    const float* w1  = (const float*)d_in[2];
    const float* b1  = (const float*)d_in[3];
    const float* w2  = (const float*)d_in[4];
    const float* b2  = (const float*)d_in[5];
    const float* W1  = (const float*)d_in[6];
    const float* B1  = (const float*)d_in[7];
    const float* W2  = (const float*)d_in[8];
    const float* B2  = (const float*)d_in[9];
    const float* L1w = (const float*)d_in[10];
    const float* L1b = (const float*)d_in[11];
    const float* g1  = (const float*)d_in[12];
    const float* be1 = (const float*)d_in[13];
    const float* L2w = (const float*)d_in[14];
    const float* L2b = (const float*)d_in[15];
    float* out = (float*)d_out;

    k_all<<<NCTA, NTHR>>>(Xa, Xc, w1, b1, w2, b2, W1, B1, W2, B2,
                          L1w, L1b, g1, be1, L2w, L2b, out);
}